// round 15
// baseline (speedup 1.0000x reference)
#include <cuda_runtime.h>

#define IN_DIM 128
#define HD     128
#define MAXN   40000
#define MAXE   640000

typedef unsigned long long u64;

// Scratch (allocation-free: __device__ globals)
__device__ float g_K[MAXN * HD];
__device__ float g_V[MAXN * HD];
__device__ int   g_cnt[MAXN];
__device__ int   g_rowptr[MAXN + 1];
__device__ int   g_cursor[MAXN];
__device__ int   g_eidx[MAXE];
__device__ int   g_srcs[MAXE];

// Packed dual-FP32 FMA (Blackwell f32x2 pipe). Each half is an independent
// IEEE fp32 fma.rn — bit-identical to two scalar __fmaf_rn.
__device__ __forceinline__ u64 fma2(u64 a, u64 b, u64 c)
{
    u64 d;
    asm("fma.rn.f32x2 %0, %1, %2, %3;" : "=l"(d) : "l"(a), "l"(b), "l"(c));
    return d;
}
__device__ __forceinline__ u64 dup2(float x)
{
    u64 d;
    asm("mov.b64 %0, {%1, %1};" : "=l"(d) : "f"(x));
    return d;
}

// ---------------------------------------------------------------------------
// CSR build: histogram by dst (4 edges per thread for MLP)
// ---------------------------------------------------------------------------
__global__ void histogram_kernel(const int* __restrict__ dst, int E)
{
    int base = (blockIdx.x * blockDim.x + threadIdx.x) * 4;
    if (base + 4 <= E) {
        int4 d = *(const int4*)&dst[base];
        atomicAdd(&g_cnt[d.x], 1);
        atomicAdd(&g_cnt[d.y], 1);
        atomicAdd(&g_cnt[d.z], 1);
        atomicAdd(&g_cnt[d.w], 1);
    } else {
        for (int e = base; e < E; e++) atomicAdd(&g_cnt[dst[e]], 1);
    }
}

// Single-block exclusive scan: int4-batched chunk sums, shfl warp scan,
// int4 write-back with in-register group prefixes. 2 block barriers total.
__global__ __launch_bounds__(1024) void scan_kernel(int n)
{
    __shared__ int wsum[32];
    const int t    = threadIdx.x;
    const int lane = t & 31;
    const int wid  = t >> 5;
    const int chunk = (n + 1023) / 1024;
    int b = t * chunk;
    int e = b + chunk;
    if (b > n) b = n;
    if (e > n) e = n;

    const bool vec = ((chunk & 3) == 0);

    int s = 0;
    if (vec) {
        for (int i = b; i + 4 <= e; i += 4) {
            int4 v = *(const int4*)&g_cnt[i];
            s += v.x + v.y + v.z + v.w;
        }
    } else {
        for (int i = b; i < e; i++) s += g_cnt[i];
    }

    int inc = s;
#pragma unroll
    for (int off = 1; off < 32; off <<= 1) {
        int x = __shfl_up_sync(0xffffffffu, inc, off);
        if (lane >= off) inc += x;
    }
    if (lane == 31) wsum[wid] = inc;
    __syncthreads();
    if (wid == 0) {
        int ws = wsum[lane];
        int winc = ws;
#pragma unroll
        for (int off = 1; off < 32; off <<= 1) {
            int x = __shfl_up_sync(0xffffffffu, winc, off);
            if (lane >= off) winc += x;
        }
        wsum[lane] = winc - ws;
    }
    __syncthreads();
    int run = wsum[wid] + inc - s;

    if (vec) {
        for (int i = b; i + 4 <= e; i += 4) {
            int4 v = *(const int4*)&g_cnt[i];
            int r0 = run;
            int r1 = r0 + v.x;
            int r2 = r1 + v.y;
            int r3 = r2 + v.z;
            int4 rp = make_int4(r0, r1, r2, r3);
            *(int4*)&g_rowptr[i] = rp;
            *(int4*)&g_cursor[i] = rp;
            run = r3 + v.w;
        }
    } else {
        for (int i = b; i < e; i++) {
            g_rowptr[i] = run;
            g_cursor[i] = run;
            run += g_cnt[i];
        }
    }
    if (t == 1023) g_rowptr[n] = run;
}

__global__ void scatter_kernel(const int* __restrict__ dst, int E)
{
    int base = (blockIdx.x * blockDim.x + threadIdx.x) * 4;
    if (base + 4 <= E) {
        int4 d = *(const int4*)&dst[base];
        int p0 = atomicAdd(&g_cursor[d.x], 1);
        int p1 = atomicAdd(&g_cursor[d.y], 1);
        int p2 = atomicAdd(&g_cursor[d.z], 1);
        int p3 = atomicAdd(&g_cursor[d.w], 1);
        g_eidx[p0] = base + 0;
        g_eidx[p1] = base + 1;
        g_eidx[p2] = base + 2;
        g_eidx[p3] = base + 3;
    } else {
        for (int e = base; e < E; e++) {
            int pos = atomicAdd(&g_cursor[dst[e]], 1);
            g_eidx[pos] = e;
        }
    }
}

// Warp-per-node rank sort (ascending edge index = reference sum order)
__global__ __launch_bounds__(256) void sortwarp_kernel(const int* __restrict__ src, int n)
{
    __shared__ int buf[8][128];
    const int warp   = (blockIdx.x * blockDim.x + threadIdx.x) >> 5;
    const int wlocal = (threadIdx.x >> 5);
    const int lane   = threadIdx.x & 31;
    if (warp >= n) return;

    const int beg = g_rowptr[warp];
    const int end = g_rowptr[warp + 1];
    const int d   = end - beg;

    if (d <= 0) return;
    if (d == 1) {
        if (lane == 0) g_srcs[beg] = src[g_eidx[beg]];
        return;
    }
    if (d <= 32) {
        int e = (lane < d) ? g_eidx[beg + lane] : 0x7fffffff;
        int r = 0;
#pragma unroll
        for (int j = 0; j < 32; j++) {
            int x = __shfl_sync(0xffffffffu, e, j);
            r += (x < e);
        }
        if (lane < d) g_srcs[beg + r] = src[e];
        return;
    }
    if (d <= 128) {
        for (int i = lane; i < d; i += 32) buf[wlocal][i] = g_eidx[beg + i];
        __syncwarp();
        for (int i = lane; i < d; i += 32) {
            int e = buf[wlocal][i];
            int r = 0;
            for (int j = 0; j < d; j++) r += (buf[wlocal][j] < e);
            g_srcs[beg + r] = src[e];
        }
    } else if (lane == 0) {
        for (int i = beg + 1; i < end; i++) {
            int key = g_eidx[i];
            int j = i - 1;
            while (j >= beg && g_eidx[j] > key) { g_eidx[j + 1] = g_eidx[j]; j--; }
            g_eidx[j + 1] = key;
        }
        for (int i = beg; i < end; i++) g_srcs[i] = src[g_eidx[i]];
    }
}

// ---------------------------------------------------------------------------
// K/V GEMM (Q removed — computed inside the aggregate), both column halves in
// one launch: blockIdx.y: 0=K, 1=V; blockIdx.z = column half.
// Measured-good inner loop (8x8 thread tile, BK=8, fma.rn.f32x2, k-ascending
// chain per element — bit-exact). Block = 128 threads -> 128x64 tile.
// ---------------------------------------------------------------------------
__global__ __launch_bounds__(128) void kv_gemm_half(
    const float* __restrict__ A,
    const float* __restrict__ WK,
    const float* __restrict__ WV,
    int M)
{
    const float* W = (blockIdx.y == 0) ? WK : WV;
    float* C = (blockIdx.y == 0) ? g_K : g_V;
    const int col0 = blockIdx.z * 64;

    __shared__ float As[8][128];   // [k][m]
    __shared__ float Bs[8][64];    // [k][n-half]

    const int tid  = threadIdx.x;   // 0..127
    const int row0 = blockIdx.x * 128;

    const int tr = (tid >> 3) * 8;
    const int tc = (tid & 7) * 8;

    const int arow = tid;
    const int brow = tid >> 4;
    const int bcol = (tid & 15) * 4;

    u64 acc2[8][4];
#pragma unroll
    for (int i = 0; i < 8; i++)
#pragma unroll
        for (int p = 0; p < 4; p++) acc2[i][p] = 0ULL;

    const bool arow_ok = (row0 + arow < M);

    for (int kc = 0; kc < IN_DIM; kc += 8) {
        float4 av0 = make_float4(0.f, 0.f, 0.f, 0.f);
        float4 av1 = make_float4(0.f, 0.f, 0.f, 0.f);
        if (arow_ok) {
            av0 = *(const float4*)&A[(row0 + arow) * IN_DIM + kc];
            av1 = *(const float4*)&A[(row0 + arow) * IN_DIM + kc + 4];
        }
        As[0][arow] = av0.x;
        As[1][arow] = av0.y;
        As[2][arow] = av0.z;
        As[3][arow] = av0.w;
        As[4][arow] = av1.x;
        As[5][arow] = av1.y;
        As[6][arow] = av1.z;
        As[7][arow] = av1.w;

        *(float4*)&Bs[brow][bcol] =
            *(const float4*)&W[(kc + brow) * HD + col0 + bcol];
        __syncthreads();

#pragma unroll
        for (int k = 0; k < 8; k++) {
            float a[8];
            *(float4*)&a[0] = *(const float4*)&As[k][tr];
            *(float4*)&a[4] = *(const float4*)&As[k][tr + 4];
            ulonglong2 bl = *(const ulonglong2*)&Bs[k][tc];
            ulonglong2 bh = *(const ulonglong2*)&Bs[k][tc + 4];
#pragma unroll
            for (int i = 0; i < 8; i++) {
                u64 ad = dup2(a[i]);
                acc2[i][0] = fma2(ad, bl.x, acc2[i][0]);
                acc2[i][1] = fma2(ad, bl.y, acc2[i][1]);
                acc2[i][2] = fma2(ad, bh.x, acc2[i][2]);
                acc2[i][3] = fma2(ad, bh.y, acc2[i][3]);
            }
        }
        __syncthreads();
    }

#pragma unroll
    for (int i = 0; i < 8; i++) {
        int r = row0 + tr + i;
        if (r < M) {
            *(ulonglong2*)&C[r * HD + col0 + tc] =
                make_ulonglong2(acc2[i][0], acc2[i][1]);
            *(ulonglong2*)&C[r * HD + col0 + tc + 4] =
                make_ulonglong2(acc2[i][2], acc2[i][3]);
        }
    }
}

// ---------------------------------------------------------------------------
// Aggregate with fused Q projection, both channel halves (blockIdx.y = half).
// Per node/channel c:
//   q    = fmaf-chain over k=0..127 of h[node][k]*WQ[k][c]   (== reference Q)
//   per edge (ascending): score = (K*q)*0.25f ; z += score ; wv += V*score
//   out  = wv / (z + 1e-6f)
// One warp per node; lane owns channel pair (64h + 2*lane, +1).
// WQ column-half staged in smem (32 KB) once per block.
// ---------------------------------------------------------------------------
__device__ __forceinline__ void edge_step2(float2 k, float2 v, const float2& q,
                                           float2& z, float2& w)
{
    float sc0 = __fmul_rn(__fmul_rn(k.x, q.x), 0.25f);
    float sc1 = __fmul_rn(__fmul_rn(k.y, q.y), 0.25f);
    z.x = __fadd_rn(z.x, sc0);
    z.y = __fadd_rn(z.y, sc1);
    w.x = __fadd_rn(w.x, __fmul_rn(v.x, sc0));
    w.y = __fadd_rn(w.y, __fmul_rn(v.y, sc1));
}

__global__ __launch_bounds__(256) void aggregate_half(
    float* __restrict__ out,
    const float* __restrict__ hfeat,
    const float* __restrict__ WQ,
    int n)
{
    // Stage WQ[:, 64h .. 64h+63] as u64 column pairs: wq2[k*32 + pair]
    __shared__ u64 wq2[128 * 32];   // 32 KB
    const int tid  = threadIdx.x;
    const int col0 = blockIdx.y * 64;

    for (int idx = tid; idx < 128 * 32; idx += 256) {
        int k = idx >> 5;
        int p = idx & 31;
        wq2[idx] = *(const u64*)&WQ[k * HD + col0 + 2 * p];
    }
    __syncthreads();

    int node = (blockIdx.x * blockDim.x + tid) >> 5;
    if (node >= n) return;
    const int lane = tid & 31;

    // ---- q = h[node] @ WQ[:, pair] : exact reference fmaf chain, k asc ----
    float4 hv = ((const float4*)hfeat)[node * 32 + lane];  // h[4lane..4lane+3]
    u64 qacc = 0ULL;
#pragma unroll 8
    for (int sl = 0; sl < 32; sl++) {
        float hx = __shfl_sync(0xffffffffu, hv.x, sl);
        float hy = __shfl_sync(0xffffffffu, hv.y, sl);
        float hz = __shfl_sync(0xffffffffu, hv.z, sl);
        float hw = __shfl_sync(0xffffffffu, hv.w, sl);
        qacc = fma2(dup2(hx), wq2[(4 * sl + 0) * 32 + lane], qacc);
        qacc = fma2(dup2(hy), wq2[(4 * sl + 1) * 32 + lane], qacc);
        qacc = fma2(dup2(hz), wq2[(4 * sl + 2) * 32 + lane], qacc);
        qacc = fma2(dup2(hw), wq2[(4 * sl + 3) * 32 + lane], qacc);
    }
    float2 q;
    asm("mov.b64 {%0, %1}, %2;" : "=f"(q.x), "=f"(q.y) : "l"(qacc));

    // ---- edge loop (R13-measured-good): float2 gathers, unroll x4 ----
    const int beg = g_rowptr[node];
    const int end = g_rowptr[node + 1];
    const int ch  = blockIdx.y * 32 + lane;

    const float2* __restrict__ K2 = (const float2*)g_K;
    const float2* __restrict__ V2 = (const float2*)g_V;

    float2 z = make_float2(0.f, 0.f);
    float2 w = make_float2(0.f, 0.f);

    int j = beg;
    for (; j + 4 <= end; j += 4) {
        int s0 = g_srcs[j + 0];
        int s1 = g_srcs[j + 1];
        int s2 = g_srcs[j + 2];
        int s3 = g_srcs[j + 3];
        float2 k0 = K2[s0 * 64 + ch], v0 = V2[s0 * 64 + ch];
        float2 k1 = K2[s1 * 64 + ch], v1 = V2[s1 * 64 + ch];
        float2 k2 = K2[s2 * 64 + ch], v2 = V2[s2 * 64 + ch];
        float2 k3 = K2[s3 * 64 + ch], v3 = V2[s3 * 64 + ch];
        edge_step2(k0, v0, q, z, w);
        edge_step2(k1, v1, q, z, w);
        edge_step2(k2, v2, q, z, w);
        edge_step2(k3, v3, q, z, w);
    }
    for (; j < end; j++) {
        int s = g_srcs[j];
        edge_step2(K2[s * 64 + ch], V2[s * 64 + ch], q, z, w);
    }

    float2 r;
    r.x = __fdiv_rn(w.x, __fadd_rn(z.x, 1e-6f));
    r.y = __fdiv_rn(w.y, __fadd_rn(z.y, 1e-6f));

    ((float2*)out)[node * 64 + ch] = r;
}

// ---------------------------------------------------------------------------
// Launch graph:
//   s2:   KV-GEMM (both halves, grid = (blocks,2,2)) -evG->
//   main: CSR chain ---- wait(evG) ---- AGG (both halves, grid.y=2)
// No AGG/GEMM overlap (measured toxic in R12). Q projection fused into AGG.
// ---------------------------------------------------------------------------
extern "C" void kernel_launch(void* const* d_in, const int* in_sizes, int n_in,
                              void* d_out, int out_size)
{
    const float* h   = (const float*)d_in[0];
    const int*   src = (const int*)  d_in[1];
    const int*   dst = (const int*)  d_in[2];
    const float* WQ  = (const float*)d_in[3];
    const float* WK  = (const float*)d_in[4];
    const float* WV  = (const float*)d_in[5];
    float* out = (float*)d_out;

    const int N = in_sizes[0] / IN_DIM;
    const int E = in_sizes[1];

    cudaStream_t s2 = nullptr;
    cudaEvent_t evG = nullptr, evFork = nullptr;
    bool forked =
        (cudaStreamCreateWithFlags(&s2, cudaStreamNonBlocking) == cudaSuccess) &&
        (cudaEventCreateWithFlags(&evFork, cudaEventDisableTiming) == cudaSuccess) &&
        (cudaEventCreateWithFlags(&evG, cudaEventDisableTiming) == cudaSuccess);

    dim3 ggrid((N + 127) / 128, 2, 2);          // K,V x column halves
    dim3 agrid((N * 32 + 255) / 256, 2);        // nodes x channel halves

    if (forked) {
        forked = (cudaEventRecord(evFork, 0) == cudaSuccess) &&
                 (cudaStreamWaitEvent(s2, evFork, 0) == cudaSuccess);
    }
    if (forked) {
        kv_gemm_half<<<ggrid, 128, 0, s2>>>(h, WK, WV, N);
        forked = (cudaEventRecord(evG, s2) == cudaSuccess);
    }

    // CSR-build chain on the main (captured) stream
    void* cntPtr = nullptr;
    cudaGetSymbolAddress(&cntPtr, g_cnt);
    cudaMemsetAsync(cntPtr, 0, (size_t)N * sizeof(int));

    const int eThreads = (E + 3) / 4;
    histogram_kernel<<<(eThreads + 511) / 512, 512>>>(dst, E);
    scan_kernel<<<1, 1024>>>(N);
    scatter_kernel<<<(eThreads + 511) / 512, 512>>>(dst, E);
    sortwarp_kernel<<<(N * 32 + 255) / 256, 256>>>(src, N);

    if (forked) {
        cudaStreamWaitEvent(0, evG, 0);
    } else {
        kv_gemm_half<<<ggrid, 128>>>(h, WK, WV, N);
    }

    aggregate_half<<<agrid, 256>>>(out, h, WQ, N);
}

// round 16
// speedup vs baseline: 1.4717x; 1.4717x over previous
#include <cuda_runtime.h>

#define IN_DIM 128
#define HD     128
#define MAXN   40000
#define MAXE   640000

typedef unsigned long long u64;

// Scratch (allocation-free: __device__ globals)
__device__ float g_Q[MAXN * HD];
__device__ float g_K[MAXN * HD];
__device__ float g_V[MAXN * HD];
__device__ int   g_cnt[MAXN];
__device__ int   g_rowptr[MAXN + 1];
__device__ int   g_cursor[MAXN];
__device__ int   g_eidx[MAXE];
__device__ int   g_srcs[MAXE];

// Packed dual-FP32 FMA (Blackwell f32x2 pipe). Each half is an independent
// IEEE fp32 fma.rn — bit-identical to two scalar __fmaf_rn.
__device__ __forceinline__ u64 fma2(u64 a, u64 b, u64 c)
{
    u64 d;
    asm("fma.rn.f32x2 %0, %1, %2, %3;" : "=l"(d) : "l"(a), "l"(b), "l"(c));
    return d;
}
__device__ __forceinline__ u64 dup2(float x)
{
    u64 d;
    asm("mov.b64 %0, {%1, %1};" : "=l"(d) : "f"(x));
    return d;
}

// ---------------------------------------------------------------------------
// CSR build: histogram by dst (4 edges per thread for MLP)
// ---------------------------------------------------------------------------
__global__ void histogram_kernel(const int* __restrict__ dst, int E)
{
    int base = (blockIdx.x * blockDim.x + threadIdx.x) * 4;
    if (base + 4 <= E) {
        int4 d = *(const int4*)&dst[base];
        atomicAdd(&g_cnt[d.x], 1);
        atomicAdd(&g_cnt[d.y], 1);
        atomicAdd(&g_cnt[d.z], 1);
        atomicAdd(&g_cnt[d.w], 1);
    } else {
        for (int e = base; e < E; e++) atomicAdd(&g_cnt[dst[e]], 1);
    }
}

// Single-block exclusive scan: int4-batched chunk sums, shfl warp scan,
// int4 write-back with in-register group prefixes. 2 block barriers total.
__global__ __launch_bounds__(1024) void scan_kernel(int n)
{
    __shared__ int wsum[32];
    const int t    = threadIdx.x;
    const int lane = t & 31;
    const int wid  = t >> 5;
    const int chunk = (n + 1023) / 1024;
    int b = t * chunk;
    int e = b + chunk;
    if (b > n) b = n;
    if (e > n) e = n;

    const bool vec = ((chunk & 3) == 0);

    int s = 0;
    if (vec) {
        for (int i = b; i + 4 <= e; i += 4) {
            int4 v = *(const int4*)&g_cnt[i];
            s += v.x + v.y + v.z + v.w;
        }
    } else {
        for (int i = b; i < e; i++) s += g_cnt[i];
    }

    int inc = s;
#pragma unroll
    for (int off = 1; off < 32; off <<= 1) {
        int x = __shfl_up_sync(0xffffffffu, inc, off);
        if (lane >= off) inc += x;
    }
    if (lane == 31) wsum[wid] = inc;
    __syncthreads();
    if (wid == 0) {
        int ws = wsum[lane];
        int winc = ws;
#pragma unroll
        for (int off = 1; off < 32; off <<= 1) {
            int x = __shfl_up_sync(0xffffffffu, winc, off);
            if (lane >= off) winc += x;
        }
        wsum[lane] = winc - ws;
    }
    __syncthreads();
    int run = wsum[wid] + inc - s;

    if (vec) {
        for (int i = b; i + 4 <= e; i += 4) {
            int4 v = *(const int4*)&g_cnt[i];
            int r0 = run;
            int r1 = r0 + v.x;
            int r2 = r1 + v.y;
            int r3 = r2 + v.z;
            int4 rp = make_int4(r0, r1, r2, r3);
            *(int4*)&g_rowptr[i] = rp;
            *(int4*)&g_cursor[i] = rp;
            run = r3 + v.w;
        }
    } else {
        for (int i = b; i < e; i++) {
            g_rowptr[i] = run;
            g_cursor[i] = run;
            run += g_cnt[i];
        }
    }
    if (t == 1023) g_rowptr[n] = run;
}

__global__ void scatter_kernel(const int* __restrict__ dst, int E)
{
    int base = (blockIdx.x * blockDim.x + threadIdx.x) * 4;
    if (base + 4 <= E) {
        int4 d = *(const int4*)&dst[base];
        int p0 = atomicAdd(&g_cursor[d.x], 1);
        int p1 = atomicAdd(&g_cursor[d.y], 1);
        int p2 = atomicAdd(&g_cursor[d.z], 1);
        int p3 = atomicAdd(&g_cursor[d.w], 1);
        g_eidx[p0] = base + 0;
        g_eidx[p1] = base + 1;
        g_eidx[p2] = base + 2;
        g_eidx[p3] = base + 3;
    } else {
        for (int e = base; e < E; e++) {
            int pos = atomicAdd(&g_cursor[dst[e]], 1);
            g_eidx[pos] = e;
        }
    }
}

// Warp-per-node rank sort (ascending edge index = reference sum order)
__global__ __launch_bounds__(256) void sortwarp_kernel(const int* __restrict__ src, int n)
{
    __shared__ int buf[8][128];
    const int warp   = (blockIdx.x * blockDim.x + threadIdx.x) >> 5;
    const int wlocal = (threadIdx.x >> 5);
    const int lane   = threadIdx.x & 31;
    if (warp >= n) return;

    const int beg = g_rowptr[warp];
    const int end = g_rowptr[warp + 1];
    const int d   = end - beg;

    if (d <= 0) return;
    if (d == 1) {
        if (lane == 0) g_srcs[beg] = src[g_eidx[beg]];
        return;
    }
    if (d <= 32) {
        int e = (lane < d) ? g_eidx[beg + lane] : 0x7fffffff;
        int r = 0;
#pragma unroll
        for (int j = 0; j < 32; j++) {
            int x = __shfl_sync(0xffffffffu, e, j);
            r += (x < e);
        }
        if (lane < d) g_srcs[beg + r] = src[e];
        return;
    }
    if (d <= 128) {
        for (int i = lane; i < d; i += 32) buf[wlocal][i] = g_eidx[beg + i];
        __syncwarp();
        for (int i = lane; i < d; i += 32) {
            int e = buf[wlocal][i];
            int r = 0;
            for (int j = 0; j < d; j++) r += (buf[wlocal][j] < e);
            g_srcs[beg + r] = src[e];
        }
    } else if (lane == 0) {
        for (int i = beg + 1; i < end; i++) {
            int key = g_eidx[i];
            int j = i - 1;
            while (j >= beg && g_eidx[j] > key) { g_eidx[j + 1] = g_eidx[j]; j--; }
            g_eidx[j + 1] = key;
        }
        for (int i = beg; i < end; i++) g_srcs[i] = src[g_eidx[i]];
    }
}

// ---------------------------------------------------------------------------
// QKV GEMM (fp32) — R8-measured-good full-tile version.
// C = A[M x 128] * W[128 x 128]  (blockIdx.y: 0=Q, 1=K, 2=V)
// Per output element: one sequential fused-FMA chain over k = 0..127
// ascending (bit-exact vs reference), packed fma.rn.f32x2 over column pairs.
// 128x128 block tile, BK=8, 256 threads, 8 rows x 8 cols per thread.
// ---------------------------------------------------------------------------
__global__ __launch_bounds__(256) void qkv_gemm(
    const float* __restrict__ A,
    const float* __restrict__ WQ,
    const float* __restrict__ WK,
    const float* __restrict__ WV,
    int M)
{
    const float* W = (blockIdx.y == 0) ? WQ : (blockIdx.y == 1) ? WK : WV;
    float* C = (blockIdx.y == 0) ? g_Q : (blockIdx.y == 1) ? g_K : g_V;

    __shared__ float As[8][128];
    __shared__ float Bs[8][128];

    const int tid  = threadIdx.x;
    const int row0 = blockIdx.x * 128;

    const int tr = (tid >> 4) * 8;
    const int tc = (tid & 15) * 8;

    const int arow  = tid >> 1;
    const int akcol = (tid & 1) * 4;
    const int brow = tid >> 5;
    const int bcol = (tid & 31) * 4;

    // acc2[i][p] = packed (C[tr+i][tc+2p], C[tr+i][tc+2p+1])
    u64 acc2[8][4];
#pragma unroll
    for (int i = 0; i < 8; i++)
#pragma unroll
        for (int p = 0; p < 4; p++) acc2[i][p] = 0ULL;

    for (int kc = 0; kc < IN_DIM; kc += 8) {
        float4 av = make_float4(0.f, 0.f, 0.f, 0.f);
        if (row0 + arow < M)
            av = *(const float4*)&A[(row0 + arow) * IN_DIM + kc + akcol];
        As[akcol + 0][arow] = av.x;
        As[akcol + 1][arow] = av.y;
        As[akcol + 2][arow] = av.z;
        As[akcol + 3][arow] = av.w;

        float4 bv = *(const float4*)&W[(kc + brow) * HD + bcol];
        *(float4*)&Bs[brow][bcol] = bv;
        __syncthreads();

#pragma unroll
        for (int k = 0; k < 8; k++) {
            float a[8];
            *(float4*)&a[0] = *(const float4*)&As[k][tr];
            *(float4*)&a[4] = *(const float4*)&As[k][tr + 4];
            ulonglong2 bl = *(const ulonglong2*)&Bs[k][tc];
            ulonglong2 bh = *(const ulonglong2*)&Bs[k][tc + 4];
#pragma unroll
            for (int i = 0; i < 8; i++) {
                u64 ad = dup2(a[i]);
                acc2[i][0] = fma2(ad, bl.x, acc2[i][0]);
                acc2[i][1] = fma2(ad, bl.y, acc2[i][1]);
                acc2[i][2] = fma2(ad, bh.x, acc2[i][2]);
                acc2[i][3] = fma2(ad, bh.y, acc2[i][3]);
            }
        }
        __syncthreads();
    }

#pragma unroll
    for (int i = 0; i < 8; i++) {
        int r = row0 + tr + i;
        if (r < M) {
            *(ulonglong2*)&C[r * HD + tc]     = make_ulonglong2(acc2[i][0], acc2[i][1]);
            *(ulonglong2*)&C[r * HD + tc + 4] = make_ulonglong2(acc2[i][2], acc2[i][3]);
        }
    }
}

// ---------------------------------------------------------------------------
// Half-channel edge aggregate (R11-measured-good, launched serially per half):
//   score = (K*Q)*0.25f ; z += score ; wv += V*score ; out = wv/(z+1e-6f)
// bit-exact ascending edge order per channel. One warp per node,
// channels [64h, 64h+64): float2 per lane.
// ---------------------------------------------------------------------------
__device__ __forceinline__ void edge_step2(float2 k, float2 v, const float2& q,
                                           float2& z, float2& w)
{
    float sc0 = __fmul_rn(__fmul_rn(k.x, q.x), 0.25f);
    float sc1 = __fmul_rn(__fmul_rn(k.y, q.y), 0.25f);
    z.x = __fadd_rn(z.x, sc0);
    z.y = __fadd_rn(z.y, sc1);
    w.x = __fadd_rn(w.x, __fmul_rn(v.x, sc0));
    w.y = __fadd_rn(w.y, __fmul_rn(v.y, sc1));
}

__global__ __launch_bounds__(256) void aggregate_half(float* __restrict__ out,
                                                      int n, int h)
{
    int node = (blockIdx.x * blockDim.x + threadIdx.x) >> 5;
    if (node >= n) return;
    const int lane = threadIdx.x & 31;
    const int ch   = h * 32 + lane;

    const int beg = g_rowptr[node];
    const int end = g_rowptr[node + 1];

    const float2* __restrict__ K2 = (const float2*)g_K;
    const float2* __restrict__ V2 = (const float2*)g_V;

    float2 q = ((const float2*)g_Q)[node * 64 + ch];

    float2 z = make_float2(0.f, 0.f);
    float2 w = make_float2(0.f, 0.f);

    int j = beg;
    for (; j + 4 <= end; j += 4) {
        int s0 = g_srcs[j + 0];
        int s1 = g_srcs[j + 1];
        int s2 = g_srcs[j + 2];
        int s3 = g_srcs[j + 3];
        float2 k0 = K2[s0 * 64 + ch], v0 = V2[s0 * 64 + ch];
        float2 k1 = K2[s1 * 64 + ch], v1 = V2[s1 * 64 + ch];
        float2 k2 = K2[s2 * 64 + ch], v2 = V2[s2 * 64 + ch];
        float2 k3 = K2[s3 * 64 + ch], v3 = V2[s3 * 64 + ch];
        edge_step2(k0, v0, q, z, w);
        edge_step2(k1, v1, q, z, w);
        edge_step2(k2, v2, q, z, w);
        edge_step2(k3, v3, q, z, w);
    }
    for (; j < end; j++) {
        int s = g_srcs[j];
        edge_step2(K2[s * 64 + ch], V2[s * 64 + ch], q, z, w);
    }

    float2 r;
    r.x = __fdiv_rn(w.x, __fadd_rn(z.x, 1e-6f));
    r.y = __fdiv_rn(w.y, __fadd_rn(z.y, 1e-6f));

    ((float2*)out)[node * 64 + ch] = r;
}

// ---------------------------------------------------------------------------
// Launch graph:
//   s2:   full QKV GEMM (one launch, grid (blocks,3)) -evG->
//   main: CSR chain ---- wait(evG) ---- AGG half 0 ---- AGG half 1
// No AGG/GEMM overlap (R12: toxic). AGG halves serialized (R11: 48+48;
// R13's concurrent halves inferred slower).
// ---------------------------------------------------------------------------
extern "C" void kernel_launch(void* const* d_in, const int* in_sizes, int n_in,
                              void* d_out, int out_size)
{
    const float* h   = (const float*)d_in[0];
    const int*   src = (const int*)  d_in[1];
    const int*   dst = (const int*)  d_in[2];
    const float* WQ  = (const float*)d_in[3];
    const float* WK  = (const float*)d_in[4];
    const float* WV  = (const float*)d_in[5];
    float* out = (float*)d_out;

    const int N = in_sizes[0] / IN_DIM;
    const int E = in_sizes[1];

    cudaStream_t s2 = nullptr;
    cudaEvent_t evG = nullptr, evFork = nullptr;
    bool forked =
        (cudaStreamCreateWithFlags(&s2, cudaStreamNonBlocking) == cudaSuccess) &&
        (cudaEventCreateWithFlags(&evFork, cudaEventDisableTiming) == cudaSuccess) &&
        (cudaEventCreateWithFlags(&evG, cudaEventDisableTiming) == cudaSuccess);

    dim3 ggrid((N + 127) / 128, 3);
    const int aggBlocks = (N * 32 + 255) / 256;

    if (forked) {
        forked = (cudaEventRecord(evFork, 0) == cudaSuccess) &&
                 (cudaStreamWaitEvent(s2, evFork, 0) == cudaSuccess);
    }
    if (forked) {
        qkv_gemm<<<ggrid, 256, 0, s2>>>(h, WQ, WK, WV, N);
        forked = (cudaEventRecord(evG, s2) == cudaSuccess);
    }

    // CSR-build chain on the main (captured) stream
    void* cntPtr = nullptr;
    cudaGetSymbolAddress(&cntPtr, g_cnt);
    cudaMemsetAsync(cntPtr, 0, (size_t)N * sizeof(int));

    const int eThreads = (E + 3) / 4;
    histogram_kernel<<<(eThreads + 511) / 512, 512>>>(dst, E);
    scan_kernel<<<1, 1024>>>(N);
    scatter_kernel<<<(eThreads + 511) / 512, 512>>>(dst, E);
    sortwarp_kernel<<<(N * 32 + 255) / 256, 256>>>(src, N);

    if (forked) {
        cudaStreamWaitEvent(0, evG, 0);
    } else {
        qkv_gemm<<<ggrid, 256>>>(h, WQ, WK, WV, N);
    }

    aggregate_half<<<aggBlocks, 256>>>(out, N, 0);
    aggregate_half<<<aggBlocks, 256>>>(out, N, 1);
}

// round 17
// speedup vs baseline: 1.5706x; 1.0672x over previous
#include <cuda_runtime.h>

#define IN_DIM 128
#define HD     128
#define MAXN   40000
#define MAXE   640000
#define SCAN_BLKS 160

typedef unsigned long long u64;

// Scratch (allocation-free: __device__ globals)
__device__ float g_Q[MAXN * HD];
__device__ float g_K[MAXN * HD];
__device__ float g_V[MAXN * HD];
__device__ int   g_cnt[MAXN];
__device__ int   g_bsum[SCAN_BLKS];
__device__ int   g_rowptr[MAXN + 1];
__device__ int   g_cursor[MAXN];
__device__ int   g_eidx[MAXE];
__device__ int   g_srcs[MAXE];

// Packed dual-FP32 FMA (Blackwell f32x2 pipe). Each half is an independent
// IEEE fp32 fma.rn — bit-identical to two scalar __fmaf_rn.
__device__ __forceinline__ u64 fma2(u64 a, u64 b, u64 c)
{
    u64 d;
    asm("fma.rn.f32x2 %0, %1, %2, %3;" : "=l"(d) : "l"(a), "l"(b), "l"(c));
    return d;
}
__device__ __forceinline__ u64 dup2(float x)
{
    u64 d;
    asm("mov.b64 %0, {%1, %1};" : "=l"(d) : "f"(x));
    return d;
}

// ---------------------------------------------------------------------------
// CSR build: histogram by dst (4 edges per thread for MLP)
// ---------------------------------------------------------------------------
__global__ void histogram_kernel(const int* __restrict__ dst, int E)
{
    int base = (blockIdx.x * blockDim.x + threadIdx.x) * 4;
    if (base + 4 <= E) {
        int4 d = *(const int4*)&dst[base];
        atomicAdd(&g_cnt[d.x], 1);
        atomicAdd(&g_cnt[d.y], 1);
        atomicAdd(&g_cnt[d.z], 1);
        atomicAdd(&g_cnt[d.w], 1);
    } else {
        for (int e = base; e < E; e++) atomicAdd(&g_cnt[dst[e]], 1);
    }
}

// Block-wide exclusive scan helper over 256 threads (shfl + smem).
// Returns this thread's exclusive prefix; *total gets the block sum.
__device__ __forceinline__ int block_exscan256(int v, int* smWarp, int* total)
{
    const int lane = threadIdx.x & 31;
    const int wid  = threadIdx.x >> 5;
    int inc = v;
#pragma unroll
    for (int off = 1; off < 32; off <<= 1) {
        int x = __shfl_up_sync(0xffffffffu, inc, off);
        if (lane >= off) inc += x;
    }
    if (lane == 31) smWarp[wid] = inc;
    __syncthreads();
    if (wid == 0 && lane < 8) {
        int ws = smWarp[lane];
        int winc = ws;
#pragma unroll
        for (int off = 1; off < 8; off <<= 1) {
            int x = __shfl_up_sync(0xffu, winc, off);
            if (lane >= off) winc += x;
        }
        smWarp[lane] = winc - ws;          // exclusive warp offsets
        if (lane == 7) smWarp[8] = winc;   // block total
    }
    __syncthreads();
    *total = smWarp[8];
    return smWarp[wid] + inc - v;
}

// scanA: per-block partial sums of g_cnt (spreads load across SMs)
__global__ __launch_bounds__(256) void scanA_kernel(int n)
{
    __shared__ int smWarp[9];
    const int chunk = (n + SCAN_BLKS - 1) / SCAN_BLKS;
    const int b0 = blockIdx.x * chunk;
    int e0 = b0 + chunk; if (e0 > n) e0 = n;

    int s = 0;
    for (int i = b0 + threadIdx.x; i < e0; i += 256) s += g_cnt[i];
    int total;
    block_exscan256(s, smWarp, &total);
    if (threadIdx.x == 0) g_bsum[blockIdx.x] = total;
}

// scanB: every block redundantly scans the 160 block sums (cheap), picks its
// offset, block-scans its chunk of g_cnt, writes rowptr + cursor.
__global__ __launch_bounds__(256) void scanB_kernel(int n)
{
    __shared__ int smWarp[9];
    __shared__ int smPref[256];
    const int t = threadIdx.x;

    int bv = (t < SCAN_BLKS) ? g_bsum[t] : 0;
    int btot;
    int bpref = block_exscan256(bv, smWarp, &btot);
    smPref[t] = bpref;
    __syncthreads();
    const int offset = smPref[blockIdx.x];
    __syncthreads();   // smWarp reused below

    const int chunk = (n + SCAN_BLKS - 1) / SCAN_BLKS;
    const int b0 = blockIdx.x * chunk;
    int e0 = b0 + chunk; if (e0 > n) e0 = n;

    // chunk <= 256 for our sizes (40000/160 = 250); guard anyway via loop
    for (int base = b0; base < e0 || base == b0; base += 256) {
        int i = base + t;
        int c = (i < e0) ? g_cnt[i] : 0;
        int tot;
        int p = block_exscan256(c, smWarp, &tot);
        if (i < e0) {
            int r = offset + p;
            g_rowptr[i] = r;
            g_cursor[i] = r;
            if (i == n - 1) g_rowptr[n] = r + c;
        }
        if (base + 256 >= e0) break;
        // (multi-iteration path would need offset += tot; not hit for n<=40960)
    }
}

__global__ void scatter_kernel(const int* __restrict__ dst, int E)
{
    int base = (blockIdx.x * blockDim.x + threadIdx.x) * 4;
    if (base + 4 <= E) {
        int4 d = *(const int4*)&dst[base];
        int p0 = atomicAdd(&g_cursor[d.x], 1);
        int p1 = atomicAdd(&g_cursor[d.y], 1);
        int p2 = atomicAdd(&g_cursor[d.z], 1);
        int p3 = atomicAdd(&g_cursor[d.w], 1);
        g_eidx[p0] = base + 0;
        g_eidx[p1] = base + 1;
        g_eidx[p2] = base + 2;
        g_eidx[p3] = base + 3;
    } else {
        for (int e = base; e < E; e++) {
            int pos = atomicAdd(&g_cursor[dst[e]], 1);
            g_eidx[pos] = e;
        }
    }
}

// Warp-per-node rank sort (ascending edge index = reference sum order)
__global__ __launch_bounds__(256) void sortwarp_kernel(const int* __restrict__ src, int n)
{
    __shared__ int buf[8][128];
    const int warp   = (blockIdx.x * blockDim.x + threadIdx.x) >> 5;
    const int wlocal = (threadIdx.x >> 5);
    const int lane   = threadIdx.x & 31;
    if (warp >= n) return;

    const int beg = g_rowptr[warp];
    const int end = g_rowptr[warp + 1];
    const int d   = end - beg;

    if (d <= 0) return;
    if (d == 1) {
        if (lane == 0) g_srcs[beg] = src[g_eidx[beg]];
        return;
    }
    if (d <= 32) {
        int e = (lane < d) ? g_eidx[beg + lane] : 0x7fffffff;
        int r = 0;
#pragma unroll
        for (int j = 0; j < 32; j++) {
            int x = __shfl_sync(0xffffffffu, e, j);
            r += (x < e);
        }
        if (lane < d) g_srcs[beg + r] = src[e];
        return;
    }
    if (d <= 128) {
        for (int i = lane; i < d; i += 32) buf[wlocal][i] = g_eidx[beg + i];
        __syncwarp();
        for (int i = lane; i < d; i += 32) {
            int e = buf[wlocal][i];
            int r = 0;
            for (int j = 0; j < d; j++) r += (buf[wlocal][j] < e);
            g_srcs[beg + r] = src[e];
        }
    } else if (lane == 0) {
        for (int i = beg + 1; i < end; i++) {
            int key = g_eidx[i];
            int j = i - 1;
            while (j >= beg && g_eidx[j] > key) { g_eidx[j + 1] = g_eidx[j]; j--; }
            g_eidx[j + 1] = key;
        }
        for (int i = beg; i < end; i++) g_srcs[i] = src[g_eidx[i]];
    }
}

// ---------------------------------------------------------------------------
// QKV GEMM (fp32) — R8/R16-measured-good full-tile version.
// C = A[M x 128] * W[128 x 128]  (blockIdx.y: 0=Q, 1=K, 2=V)
// Per output element: one sequential fused-FMA chain over k = 0..127
// ascending (bit-exact vs reference), packed fma.rn.f32x2 over column pairs.
// 128x128 block tile, BK=8, 256 threads, 8 rows x 8 cols per thread.
// ---------------------------------------------------------------------------
__global__ __launch_bounds__(256) void qkv_gemm(
    const float* __restrict__ A,
    const float* __restrict__ WQ,
    const float* __restrict__ WK,
    const float* __restrict__ WV,
    int M)
{
    const float* W = (blockIdx.y == 0) ? WQ : (blockIdx.y == 1) ? WK : WV;
    float* C = (blockIdx.y == 0) ? g_Q : (blockIdx.y == 1) ? g_K : g_V;

    __shared__ float As[8][128];
    __shared__ float Bs[8][128];

    const int tid  = threadIdx.x;
    const int row0 = blockIdx.x * 128;

    const int tr = (tid >> 4) * 8;
    const int tc = (tid & 15) * 8;

    const int arow  = tid >> 1;
    const int akcol = (tid & 1) * 4;
    const int brow = tid >> 5;
    const int bcol = (tid & 31) * 4;

    u64 acc2[8][4];
#pragma unroll
    for (int i = 0; i < 8; i++)
#pragma unroll
        for (int p = 0; p < 4; p++) acc2[i][p] = 0ULL;

    for (int kc = 0; kc < IN_DIM; kc += 8) {
        float4 av = make_float4(0.f, 0.f, 0.f, 0.f);
        if (row0 + arow < M)
            av = *(const float4*)&A[(row0 + arow) * IN_DIM + kc + akcol];
        As[akcol + 0][arow] = av.x;
        As[akcol + 1][arow] = av.y;
        As[akcol + 2][arow] = av.z;
        As[akcol + 3][arow] = av.w;

        float4 bv = *(const float4*)&W[(kc + brow) * HD + bcol];
        *(float4*)&Bs[brow][bcol] = bv;
        __syncthreads();

#pragma unroll
        for (int k = 0; k < 8; k++) {
            float a[8];
            *(float4*)&a[0] = *(const float4*)&As[k][tr];
            *(float4*)&a[4] = *(const float4*)&As[k][tr + 4];
            ulonglong2 bl = *(const ulonglong2*)&Bs[k][tc];
            ulonglong2 bh = *(const ulonglong2*)&Bs[k][tc + 4];
#pragma unroll
            for (int i = 0; i < 8; i++) {
                u64 ad = dup2(a[i]);
                acc2[i][0] = fma2(ad, bl.x, acc2[i][0]);
                acc2[i][1] = fma2(ad, bl.y, acc2[i][1]);
                acc2[i][2] = fma2(ad, bh.x, acc2[i][2]);
                acc2[i][3] = fma2(ad, bh.y, acc2[i][3]);
            }
        }
        __syncthreads();
    }

#pragma unroll
    for (int i = 0; i < 8; i++) {
        int r = row0 + tr + i;
        if (r < M) {
            *(ulonglong2*)&C[r * HD + tc]     = make_ulonglong2(acc2[i][0], acc2[i][1]);
            *(ulonglong2*)&C[r * HD + tc + 4] = make_ulonglong2(acc2[i][2], acc2[i][3]);
        }
    }
}

// ---------------------------------------------------------------------------
// Half-channel edge aggregate (R11/R16-measured-good, serial per half):
//   score = (K*Q)*0.25f ; z += score ; wv += V*score ; out = wv/(z+1e-6f)
// bit-exact ascending edge order per channel. One warp per node,
// channels [64h, 64h+64): float2 per lane.
// ---------------------------------------------------------------------------
__device__ __forceinline__ void edge_step2(float2 k, float2 v, const float2& q,
                                           float2& z, float2& w)
{
    float sc0 = __fmul_rn(__fmul_rn(k.x, q.x), 0.25f);
    float sc1 = __fmul_rn(__fmul_rn(k.y, q.y), 0.25f);
    z.x = __fadd_rn(z.x, sc0);
    z.y = __fadd_rn(z.y, sc1);
    w.x = __fadd_rn(w.x, __fmul_rn(v.x, sc0));
    w.y = __fadd_rn(w.y, __fmul_rn(v.y, sc1));
}

__global__ __launch_bounds__(256) void aggregate_half(float* __restrict__ out,
                                                      int n, int h)
{
    int node = (blockIdx.x * blockDim.x + threadIdx.x) >> 5;
    if (node >= n) return;
    const int lane = threadIdx.x & 31;
    const int ch   = h * 32 + lane;

    const int beg = g_rowptr[node];
    const int end = g_rowptr[node + 1];

    const float2* __restrict__ K2 = (const float2*)g_K;
    const float2* __restrict__ V2 = (const float2*)g_V;

    float2 q = ((const float2*)g_Q)[node * 64 + ch];

    float2 z = make_float2(0.f, 0.f);
    float2 w = make_float2(0.f, 0.f);

    int j = beg;
    for (; j + 4 <= end; j += 4) {
        int s0 = g_srcs[j + 0];
        int s1 = g_srcs[j + 1];
        int s2 = g_srcs[j + 2];
        int s3 = g_srcs[j + 3];
        float2 k0 = K2[s0 * 64 + ch], v0 = V2[s0 * 64 + ch];
        float2 k1 = K2[s1 * 64 + ch], v1 = V2[s1 * 64 + ch];
        float2 k2 = K2[s2 * 64 + ch], v2 = V2[s2 * 64 + ch];
        float2 k3 = K2[s3 * 64 + ch], v3 = V2[s3 * 64 + ch];
        edge_step2(k0, v0, q, z, w);
        edge_step2(k1, v1, q, z, w);
        edge_step2(k2, v2, q, z, w);
        edge_step2(k3, v3, q, z, w);
    }
    for (; j < end; j++) {
        int s = g_srcs[j];
        edge_step2(K2[s * 64 + ch], V2[s * 64 + ch], q, z, w);
    }

    float2 r;
    r.x = __fdiv_rn(w.x, __fadd_rn(z.x, 1e-6f));
    r.y = __fdiv_rn(w.y, __fadd_rn(z.y, 1e-6f));

    ((float2*)out)[node * 64 + ch] = r;
}

// ---------------------------------------------------------------------------
// Launch graph:
//   s2:   full QKV GEMM -evG->
//   main: memset, hist, scanA, scanB, scatter, sort -- wait(evG) -- AGG0, AGG1
// No AGG/GEMM overlap (R12: toxic). AGG halves serialized (R16-measured-good).
// ---------------------------------------------------------------------------
extern "C" void kernel_launch(void* const* d_in, const int* in_sizes, int n_in,
                              void* d_out, int out_size)
{
    const float* h   = (const float*)d_in[0];
    const int*   src = (const int*)  d_in[1];
    const int*   dst = (const int*)  d_in[2];
    const float* WQ  = (const float*)d_in[3];
    const float* WK  = (const float*)d_in[4];
    const float* WV  = (const float*)d_in[5];
    float* out = (float*)d_out;

    const int N = in_sizes[0] / IN_DIM;
    const int E = in_sizes[1];

    cudaStream_t s2 = nullptr;
    cudaEvent_t evG = nullptr, evFork = nullptr;
    bool forked =
        (cudaStreamCreateWithFlags(&s2, cudaStreamNonBlocking) == cudaSuccess) &&
        (cudaEventCreateWithFlags(&evFork, cudaEventDisableTiming) == cudaSuccess) &&
        (cudaEventCreateWithFlags(&evG, cudaEventDisableTiming) == cudaSuccess);

    dim3 ggrid((N + 127) / 128, 3);
    const int aggBlocks = (N * 32 + 255) / 256;

    if (forked) {
        forked = (cudaEventRecord(evFork, 0) == cudaSuccess) &&
                 (cudaStreamWaitEvent(s2, evFork, 0) == cudaSuccess);
    }
    if (forked) {
        qkv_gemm<<<ggrid, 256, 0, s2>>>(h, WQ, WK, WV, N);
        forked = (cudaEventRecord(evG, s2) == cudaSuccess);
    }

    // CSR-build chain on the main (captured) stream
    void* cntPtr = nullptr;
    cudaGetSymbolAddress(&cntPtr, g_cnt);
    cudaMemsetAsync(cntPtr, 0, (size_t)N * sizeof(int));

    const int eThreads = (E + 3) / 4;
    histogram_kernel<<<(eThreads + 511) / 512, 512>>>(dst, E);
    scanA_kernel<<<SCAN_BLKS, 256>>>(N);
    scanB_kernel<<<SCAN_BLKS, 256>>>(N);
    scatter_kernel<<<(eThreads + 511) / 512, 512>>>(dst, E);
    sortwarp_kernel<<<(N * 32 + 255) / 256, 256>>>(src, N);

    if (forked) {
        cudaStreamWaitEvent(0, evG, 0);
    } else {
        qkv_gemm<<<ggrid, 256>>>(h, WQ, WK, WV, N);
    }

    aggregate_half<<<aggBlocks, 256>>>(out, N, 0);
    aggregate_half<<<aggBlocks, 256>>>(out, N, 1);
}